// round 2
// baseline (speedup 1.0000x reference)
#include <cuda_runtime.h>
#include <cuda_bf16.h>
#include <math.h>

// Problem constants
#define NN    4096
#define NFEAT 64
#define NHID  64
#define NCLS  32
#define NG    3
#define NR    2

// ---------------- device scratch (static, no allocation) ----------------
__device__ float g_s1[NG * NR * NN * NHID];   // 6.3 MB
__device__ float g_h1[NG * NN * NHID];        // 3.1 MB
__device__ float g_xh[NN * NHID];             // 1  MB
__device__ float g_s2[NG * NR * NN * NCLS];   // 3.1 MB
__device__ float g_h2[NG * NN * NCLS];        // 1.6 MB
__device__ float g_p1[NG * 64];
__device__ float g_p2[NG * 64];
__device__ float g_a1[NG];
__device__ float g_a2[NG];

// ---------------- helpers ----------------
__device__ __forceinline__ unsigned f2tf(float x) {
    unsigned r;
    asm("cvt.rna.tf32.f32 %0, %1;" : "=r"(r) : "f"(x));
    return r;
}

__device__ __forceinline__ void mma_tf32(float* d, const unsigned* a, const unsigned* b) {
    asm volatile(
        "mma.sync.aligned.m16n8k8.row.col.f32.tf32.tf32.f32 "
        "{%0,%1,%2,%3}, {%4,%5,%6,%7}, {%8,%9}, {%0,%1,%2,%3};"
        : "+f"(d[0]), "+f"(d[1]), "+f"(d[2]), "+f"(d[3])
        : "r"(a[0]), "r"(a[1]), "r"(a[2]), "r"(a[3]), "r"(b[0]), "r"(b[1]));
}

__device__ __forceinline__ void cp16(void* smem_dst, const void* gsrc) {
    unsigned d = (unsigned)__cvta_generic_to_shared(smem_dst);
    asm volatile("cp.async.cg.shared.global [%0], [%1], 16;" :: "r"(d), "l"(gsrc));
}
#define CP_COMMIT() asm volatile("cp.async.commit_group;")
#define CP_WAIT1()  asm volatile("cp.async.wait_group 1;")
#define CP_WAIT0()  asm volatile("cp.async.wait_group 0;")

// ---------------- small fp32 GEMM: OUT[gr] = IN @ W[gr] ----------------
// IN: [4096][64], W: [6][64][NOUT], OUT: [6][4096][NOUT]
template <int NOUT>
__global__ void __launch_bounds__(256) small_gemm(const float* __restrict__ IN,
                                                  const float* __restrict__ W,
                                                  float* __restrict__ OUT) {
    __shared__ float Xs[64][65];
    __shared__ float Ws[64][NOUT + 1];
    const int tid  = threadIdx.x;
    const int row0 = blockIdx.x * 64;
    const int gr   = blockIdx.y;

#pragma unroll
    for (int it = 0; it < 16; ++it) {
        int idx = tid + it * 256;
        Xs[idx >> 6][idx & 63] = IN[(size_t)(row0 + (idx >> 6)) * 64 + (idx & 63)];
    }
    const float* Wg = W + (size_t)gr * 64 * NOUT;
#pragma unroll
    for (int it = 0; it < (64 * NOUT) / 256; ++it) {
        int idx = tid + it * 256;
        Ws[idx / NOUT][idx % NOUT] = Wg[idx];
    }
    __syncthreads();

    constexpr int TX  = NOUT / 4;   // 16 or 8
    constexpr int TY  = 256 / TX;   // 16 or 32
    constexpr int RPT = 64 / TY;    // 4 or 2
    const int tx = tid % TX, ty = tid / TX;
    const int c0 = tx * 4, r0 = ty * RPT;

    float acc[RPT][4];
#pragma unroll
    for (int i = 0; i < RPT; ++i)
#pragma unroll
        for (int j = 0; j < 4; ++j) acc[i][j] = 0.f;

#pragma unroll
    for (int k = 0; k < 64; ++k) {
        float bb[4];
#pragma unroll
        for (int j = 0; j < 4; ++j) bb[j] = Ws[k][c0 + j];
#pragma unroll
        for (int i = 0; i < RPT; ++i) {
            float av = Xs[r0 + i][k];
#pragma unroll
            for (int j = 0; j < 4; ++j) acc[i][j] = fmaf(av, bb[j], acc[i][j]);
        }
    }
    float* Og = OUT + ((size_t)gr * NN + row0) * NOUT;
#pragma unroll
    for (int i = 0; i < RPT; ++i)
#pragma unroll
        for (int j = 0; j < 4; ++j)
            Og[(size_t)(r0 + i) * NOUT + c0 + j] = acc[i][j];
}

// ---------------- big GEMM: H[g] = relu(sum_r adj[g,r] @ S[g,r] + b[g]) ----------------
// adj: [3][2][4096][4096] f32, S: [3][2][4096][NOUT], bias: [3][NOUT]
// H: [3][4096][NOUT], parts: [3][64] per-CTA partial sums (deterministic)
// grid (64, 3), 128 threads. TM=64, KB=32, tf32 mma.
template <int NOUT, int WARPS_N, int WM, int WN>
__global__ void __launch_bounds__(128) big_gemm(const float* __restrict__ adj,
                                                const float* __restrict__ S,
                                                const float* __restrict__ bias,
                                                float* __restrict__ H,
                                                float* __restrict__ parts) {
    constexpr int TM  = 64;
    constexpr int KB  = 32;
    constexpr int TNP = NOUT + 8;   // bank stride mod 32 == 8 -> conflict free
    constexpr int MI  = WM / 16;
    constexpr int NJ  = WN / 8;

    __shared__ float As[2][TM][36]; // 36 mod 32 == 4 -> conflict free frag loads
    __shared__ float Bs[2][KB][TNP];

    const int g    = blockIdx.y;
    const int row0 = blockIdx.x * TM;
    const int tid  = threadIdx.x;
    const int warp = tid >> 5, lane = tid & 31;
    const int gid  = lane >> 2, tg = lane & 3;
    const int wm   = warp / WARPS_N, wn = warp % WARPS_N;
    const int wrow = wm * WM, wcol = wn * WN;

    float acc[MI][NJ][4];
#pragma unroll
    for (int i = 0; i < MI; ++i)
#pragma unroll
        for (int j = 0; j < NJ; ++j)
#pragma unroll
            for (int q = 0; q < 4; ++q) acc[i][j][q] = 0.f;

    const size_t adj_g = (size_t)g * NR * NN * NN;
    const size_t s_g   = (size_t)g * NR * NN * NOUT;

    auto load_chunk = [&](int buf, int c) {
        const int role = c >> 7;
        const int kb   = c & 127;
        const float* Ab = adj + adj_g + (size_t)role * NN * NN + (size_t)row0 * NN + kb * KB;
#pragma unroll
        for (int it = 0; it < 4; ++it) {
            int cid = tid + it * 128;
            int r = cid >> 3, s4 = (cid & 7) * 4;
            cp16(&As[buf][r][s4], Ab + (size_t)r * NN + s4);
        }
        const float* Bb = S + s_g + (size_t)role * NN * NOUT + (size_t)kb * KB * NOUT;
        constexpr int SEGS = NOUT / 4;
#pragma unroll
        for (int it = 0; it < (KB * NOUT / 4) / 128; ++it) {
            int cid = tid + it * 128;
            int r = cid / SEGS, s4 = (cid % SEGS) * 4;
            cp16(&Bs[buf][r][s4], Bb + r * NOUT + s4);
        }
    };

    constexpr int NCH = NR * (NN / KB);   // 256
    load_chunk(0, 0);
    CP_COMMIT();

    for (int c = 0; c < NCH; ++c) {
        if (c + 1 < NCH) {
            load_chunk((c + 1) & 1, c + 1);
            CP_COMMIT();
            CP_WAIT1();
        } else {
            CP_WAIT0();
        }
        __syncthreads();
        const int buf = c & 1;
#pragma unroll
        for (int ks = 0; ks < KB / 8; ++ks) {
            const int k0 = ks * 8;
            unsigned afr[MI][4];
#pragma unroll
            for (int i = 0; i < MI; ++i) {
                int rb = wrow + i * 16;
                afr[i][0] = f2tf(As[buf][rb + gid][k0 + tg]);
                afr[i][1] = f2tf(As[buf][rb + gid + 8][k0 + tg]);
                afr[i][2] = f2tf(As[buf][rb + gid][k0 + tg + 4]);
                afr[i][3] = f2tf(As[buf][rb + gid + 8][k0 + tg + 4]);
            }
            unsigned bfr[NJ][2];
#pragma unroll
            for (int j = 0; j < NJ; ++j) {
                int cb = wcol + j * 8 + gid;
                bfr[j][0] = f2tf(Bs[buf][k0 + tg][cb]);
                bfr[j][1] = f2tf(Bs[buf][k0 + tg + 4][cb]);
            }
#pragma unroll
            for (int i = 0; i < MI; ++i)
#pragma unroll
                for (int j = 0; j < NJ; ++j)
                    mma_tf32(acc[i][j], afr[i], bfr[j]);
        }
        __syncthreads();
    }

    // epilogue: bias + relu + store + partial sum
    float lsum = 0.f;
    const float* bv = bias + g * NOUT;
    float* Hg = H + ((size_t)g * NN + row0) * NOUT;
#pragma unroll
    for (int i = 0; i < MI; ++i) {
#pragma unroll
        for (int j = 0; j < NJ; ++j) {
            const int r0 = wrow + i * 16 + gid;
            const int cc = wcol + j * 8 + tg * 2;
            const float b0 = bv[cc], b1v = bv[cc + 1];
            float v0 = fmaxf(acc[i][j][0] + b0, 0.f);
            float v1 = fmaxf(acc[i][j][1] + b1v, 0.f);
            float v2 = fmaxf(acc[i][j][2] + b0, 0.f);
            float v3 = fmaxf(acc[i][j][3] + b1v, 0.f);
            Hg[(size_t)r0 * NOUT + cc]           = v0;
            Hg[(size_t)r0 * NOUT + cc + 1]       = v1;
            Hg[(size_t)(r0 + 8) * NOUT + cc]     = v2;
            Hg[(size_t)(r0 + 8) * NOUT + cc + 1] = v3;
            lsum += v0 + v1 + v2 + v3;
        }
    }
#pragma unroll
    for (int off = 16; off; off >>= 1) lsum += __shfl_xor_sync(0xffffffffu, lsum, off);
    __shared__ float wsum[4];
    if (lane == 0) wsum[warp] = lsum;
    __syncthreads();
    if (tid == 0)
        parts[g * 64 + blockIdx.x] = wsum[0] + wsum[1] + wsum[2] + wsum[3];
}

// ---------------- attention over genes ----------------
// parts: [3][64] partial sums; a_out: [3] softmax weights
__global__ void attn_kernel(const float* __restrict__ parts,
                            const float* __restrict__ Wk,
                            const float* __restrict__ Wq,
                            int layer, float inv_cnt,
                            float* __restrict__ a_out) {
    __shared__ float ssq[NG];
    const int tid = threadIdx.x;   // 96 threads: 3 warps, one per gene
    const int g = tid >> 5, lane = tid & 31;
    float v = parts[g * 64 + lane] + parts[g * 64 + 32 + lane];
#pragma unroll
    for (int off = 16; off; off >>= 1) v += __shfl_xor_sync(0xffffffffu, v, off);
    if (lane == 0) ssq[g] = v * inv_cnt;
    __syncthreads();
    if (tid == 0) {
        const float* wk = Wk + layer * 9;
        const float* wq = Wq + layer * 9;
        float kk[NG], lg[NG];
#pragma unroll
        for (int j = 0; j < NG; ++j)
            kk[j] = fmaxf(ssq[0] * wk[j] + ssq[1] * wk[3 + j] + ssq[2] * wk[6 + j], 0.f);
        float m = -1e30f;
#pragma unroll
        for (int j = 0; j < NG; ++j) {
            lg[j] = kk[0] * wq[j] + kk[1] * wq[3 + j] + kk[2] * wq[6 + j];
            m = fmaxf(m, lg[j]);
        }
        float e0 = expf(lg[0] - m), e1 = expf(lg[1] - m), e2 = expf(lg[2] - m);
        float inv = 1.f / (e0 + e1 + e2);
        a_out[0] = e0 * inv;
        a_out[1] = e1 * inv;
        a_out[2] = e2 * inv;
    }
}

// ---------------- attention-weighted combine: out = sum_g a[g] * H[g] ----------------
__global__ void combine_kernel(const float* __restrict__ H,
                               const float* __restrict__ a,
                               float* __restrict__ out, int nd) {
    const int i = blockIdx.x * blockDim.x + threadIdx.x;   // float4 index
    const int q = nd >> 2;
    if (i >= q) return;
    const float a0 = a[0], a1 = a[1], a2 = a[2];
    const float4* h = (const float4*)H;
    float4 x0 = h[i], x1 = h[i + q], x2 = h[i + 2 * q];
    float4 r;
    r.x = a0 * x0.x + a1 * x1.x + a2 * x2.x;
    r.y = a0 * x0.y + a1 * x1.y + a2 * x2.y;
    r.z = a0 * x0.z + a1 * x1.z + a2 * x2.z;
    r.w = a0 * x0.w + a1 * x1.w + a2 * x2.w;
    ((float4*)out)[i] = r;
}

// ---------------- launch ----------------
extern "C" void kernel_launch(void* const* d_in, const int* in_sizes, int n_in,
                              void* d_out, int out_size) {
    const float* x   = (const float*)d_in[0];
    const float* adj = (const float*)d_in[1];
    const float* W1  = (const float*)d_in[2];
    const float* b1  = (const float*)d_in[3];
    const float* W2  = (const float*)d_in[4];
    const float* b2  = (const float*)d_in[5];
    const float* Wk  = (const float*)d_in[6];
    const float* Wq  = (const float*)d_in[7];
    float* out = (float*)d_out;

    float *s1, *h1, *xh, *s2, *h2, *p1, *p2, *a1, *a2;
    cudaGetSymbolAddress((void**)&s1, g_s1);
    cudaGetSymbolAddress((void**)&h1, g_h1);
    cudaGetSymbolAddress((void**)&xh, g_xh);
    cudaGetSymbolAddress((void**)&s2, g_s2);
    cudaGetSymbolAddress((void**)&h2, g_h2);
    cudaGetSymbolAddress((void**)&p1, g_p1);
    cudaGetSymbolAddress((void**)&p2, g_p2);
    cudaGetSymbolAddress((void**)&a1, g_a1);
    cudaGetSymbolAddress((void**)&a2, g_a2);

    // Layer 1
    small_gemm<NHID><<<dim3(NN / 64, NG * NR), 256>>>(x, W1, s1);
    big_gemm<NHID, 2, 32, 32><<<dim3(64, NG), 128>>>(adj, s1, b1, h1, p1);
    attn_kernel<<<1, 96>>>(p1, Wk, Wq, 0, 1.f / ((float)NN * NHID), a1);
    combine_kernel<<<(NN * NHID / 4 + 255) / 256, 256>>>(h1, a1, xh, NN * NHID);

    // Layer 2
    small_gemm<NCLS><<<dim3(NN / 64, NG * NR), 256>>>(xh, W2, s2);
    big_gemm<NCLS, 1, 16, 32><<<dim3(64, NG), 128>>>(adj, s2, b2, h2, p2);
    attn_kernel<<<1, 96>>>(p2, Wk, Wq, 1, 1.f / ((float)NN * NCLS), a2);
    combine_kernel<<<(NN * NCLS / 4 + 255) / 256, 256>>>(h2, a2, out, NN * NCLS);
}

// round 3
// speedup vs baseline: 1.4344x; 1.4344x over previous
#include <cuda_runtime.h>
#include <cuda_bf16.h>
#include <math.h>

// Problem constants
#define NN    4096
#define NFEAT 64
#define NHID  64
#define NCLS  32
#define NG    3
#define NR    2

// ---------------- device scratch (static, no allocation) ----------------
__device__ float g_s1[NG * NR * NN * NHID];   // tf32-rounded S, layer 1
__device__ float g_hp1[NG * NR * NN * NHID];  // per-role partials, layer 1
__device__ float g_h1[NG * NN * NHID];
__device__ float g_xh[NN * NHID];
__device__ float g_s2[NG * NR * NN * NCLS];
__device__ float g_hp2[NG * NR * NN * NCLS];
__device__ float g_h2[NG * NN * NCLS];
__device__ float g_p1[NG * 64];
__device__ float g_p2[NG * 64];
__device__ float g_a1[NG];
__device__ float g_a2[NG];

// ---------------- helpers ----------------
__device__ __forceinline__ unsigned f2tf(float x) {
    unsigned r;
    asm("cvt.rna.tf32.f32 %0, %1;" : "=r"(r) : "f"(x));
    return r;
}

__device__ __forceinline__ void mma_tf32(float* d, const unsigned* a, const unsigned* b) {
    asm volatile(
        "mma.sync.aligned.m16n8k8.row.col.f32.tf32.tf32.f32 "
        "{%0,%1,%2,%3}, {%4,%5,%6,%7}, {%8,%9}, {%0,%1,%2,%3};"
        : "+f"(d[0]), "+f"(d[1]), "+f"(d[2]), "+f"(d[3])
        : "r"(a[0]), "r"(a[1]), "r"(a[2]), "r"(a[3]), "r"(b[0]), "r"(b[1]));
}

__device__ __forceinline__ void cp16(void* smem_dst, const void* gsrc) {
    unsigned d = (unsigned)__cvta_generic_to_shared(smem_dst);
    asm volatile("cp.async.cg.shared.global [%0], [%1], 16;" :: "r"(d), "l"(gsrc));
}
#define CP_COMMIT() asm volatile("cp.async.commit_group;")
#define CP_WAIT1()  asm volatile("cp.async.wait_group 1;")
#define CP_WAIT0()  asm volatile("cp.async.wait_group 0;")

// ---------------- small fp32 GEMM: OUT[gr] = tf32(IN @ W[gr]) ----------------
// IN: [4096][64], W: [6][64][NOUT], OUT: [6][4096][NOUT] (stored tf32-rounded)
template <int NOUT>
__global__ void __launch_bounds__(256) small_gemm(const float* __restrict__ IN,
                                                  const float* __restrict__ W,
                                                  float* __restrict__ OUT) {
    __shared__ float Xs[64][65];
    __shared__ float Ws[64][NOUT + 1];
    const int tid  = threadIdx.x;
    const int row0 = blockIdx.x * 64;
    const int gr   = blockIdx.y;

#pragma unroll
    for (int it = 0; it < 16; ++it) {
        int idx = tid + it * 256;
        Xs[idx >> 6][idx & 63] = IN[(size_t)(row0 + (idx >> 6)) * 64 + (idx & 63)];
    }
    const float* Wg = W + (size_t)gr * 64 * NOUT;
#pragma unroll
    for (int it = 0; it < (64 * NOUT) / 256; ++it) {
        int idx = tid + it * 256;
        Ws[idx / NOUT][idx % NOUT] = Wg[idx];
    }
    __syncthreads();

    constexpr int TX  = NOUT / 4;   // 16 or 8
    constexpr int TY  = 256 / TX;   // 16 or 32
    constexpr int RPT = 64 / TY;    // 4 or 2
    const int tx = tid % TX, ty = tid / TX;
    const int c0 = tx * 4, r0 = ty * RPT;

    float acc[RPT][4];
#pragma unroll
    for (int i = 0; i < RPT; ++i)
#pragma unroll
        for (int j = 0; j < 4; ++j) acc[i][j] = 0.f;

#pragma unroll
    for (int k = 0; k < 64; ++k) {
        float bb[4];
#pragma unroll
        for (int j = 0; j < 4; ++j) bb[j] = Ws[k][c0 + j];
#pragma unroll
        for (int i = 0; i < RPT; ++i) {
            float av = Xs[r0 + i][k];
#pragma unroll
            for (int j = 0; j < 4; ++j) acc[i][j] = fmaf(av, bb[j], acc[i][j]);
        }
    }
    float* Og = OUT + ((size_t)gr * NN + row0) * NOUT;
#pragma unroll
    for (int i = 0; i < RPT; ++i)
#pragma unroll
        for (int j = 0; j < 4; ++j)
            Og[(size_t)(r0 + i) * NOUT + c0 + j] = __uint_as_float(f2tf(acc[i][j]));
}

// ---------------- big GEMM (role-split): Hp[g,r] = adj[g,r] @ S[g,r] ----------------
// grid (64, 3, 2), 128 threads. TM=64, K=4096 per CTA, KB=32, tf32 mma.
// B (S) is pre-rounded to tf32 by the producer -> raw-bit loads, no in-loop cvt.
template <int NOUT>
__global__ void __launch_bounds__(128) big_gemm2(const float* __restrict__ adj,
                                                 const float* __restrict__ S,
                                                 float* __restrict__ Hp) {
    constexpr int TM  = 64;
    constexpr int KB  = 32;
    constexpr int BP  = NOUT + 8;             // stride mod 32 == 8 -> conflict free
    constexpr int WN  = (NOUT == 64) ? 32 : 16;
    constexpr int MI  = 2;                    // WM = 32
    constexpr int NJ  = WN / 8;

    __shared__ float As[2][TM][36];           // 36 mod 32 == 4 -> conflict free
    __shared__ float Bs[2][KB][BP];

    const int g    = blockIdx.y;
    const int role = blockIdx.z;
    const int row0 = blockIdx.x * TM;
    const int tid  = threadIdx.x;
    const int warp = tid >> 5, lane = tid & 31;
    const int gid  = lane >> 2, tg = lane & 3;
    const int wm   = warp >> 1, wn = warp & 1; // 2x2 warp grid
    const int wrow = wm * 32, wcol = wn * WN;

    float acc[MI][NJ][4];
#pragma unroll
    for (int i = 0; i < MI; ++i)
#pragma unroll
        for (int j = 0; j < NJ; ++j)
#pragma unroll
            for (int q = 0; q < 4; ++q) acc[i][j][q] = 0.f;

    const float* Ag = adj + ((size_t)(g * NR + role) * NN + row0) * NN;
    const float* Sg = S + (size_t)(g * NR + role) * NN * NOUT;

    auto load_chunk = [&](int buf, int c) {
#pragma unroll
        for (int it = 0; it < 4; ++it) {
            int cid = tid + it * 128;
            int r = cid >> 3, s4 = (cid & 7) * 4;
            cp16(&As[buf][r][s4], Ag + (size_t)r * NN + c * KB + s4);
        }
        constexpr int SEGS = NOUT / 4;
#pragma unroll
        for (int it = 0; it < (KB * NOUT / 4) / 128; ++it) {
            int cid = tid + it * 128;
            int r = cid / SEGS, s4 = (cid % SEGS) * 4;
            cp16(&Bs[buf][r][s4], Sg + (size_t)(c * KB + r) * NOUT + s4);
        }
    };

    constexpr int NCH = NN / KB;   // 128
    load_chunk(0, 0);
    CP_COMMIT();

    for (int c = 0; c < NCH; ++c) {
        if (c + 1 < NCH) {
            load_chunk((c + 1) & 1, c + 1);
            CP_COMMIT();
            CP_WAIT1();
        } else {
            CP_WAIT0();
        }
        __syncthreads();
        const int buf = c & 1;
#pragma unroll
        for (int ks = 0; ks < KB / 8; ++ks) {
            const int k0 = ks * 8;
            unsigned afr[MI][4];
#pragma unroll
            for (int i = 0; i < MI; ++i) {
                int rb = wrow + i * 16;
                afr[i][0] = f2tf(As[buf][rb + gid][k0 + tg]);
                afr[i][1] = f2tf(As[buf][rb + gid + 8][k0 + tg]);
                afr[i][2] = f2tf(As[buf][rb + gid][k0 + tg + 4]);
                afr[i][3] = f2tf(As[buf][rb + gid + 8][k0 + tg + 4]);
            }
            unsigned bfr[NJ][2];
#pragma unroll
            for (int j = 0; j < NJ; ++j) {
                int cb = wcol + j * 8 + gid;
                bfr[j][0] = __float_as_uint(Bs[buf][k0 + tg][cb]);
                bfr[j][1] = __float_as_uint(Bs[buf][k0 + tg + 4][cb]);
            }
#pragma unroll
            for (int i = 0; i < MI; ++i)
#pragma unroll
                for (int j = 0; j < NJ; ++j)
                    mma_tf32(acc[i][j], afr[i], bfr[j]);
        }
        __syncthreads();
    }

    // store partials (no bias/relu here — fuse kernel adds roles)
    float* Hg = Hp + ((size_t)(g * NR + role) * NN + row0) * NOUT;
#pragma unroll
    for (int i = 0; i < MI; ++i) {
#pragma unroll
        for (int j = 0; j < NJ; ++j) {
            const int r0 = wrow + i * 16 + gid;
            const int cc = wcol + j * 8 + tg * 2;
            float2 v01 = make_float2(acc[i][j][0], acc[i][j][1]);
            float2 v23 = make_float2(acc[i][j][2], acc[i][j][3]);
            *(float2*)&Hg[(size_t)r0 * NOUT + cc]       = v01;
            *(float2*)&Hg[(size_t)(r0 + 8) * NOUT + cc] = v23;
        }
    }
}

// ---------------- fuse: H[g] = relu(Hp[g,0] + Hp[g,1] + b[g]), + partial sums ----------------
// grid (64, 3), 256 threads. parts: [3][64]
template <int NOUT>
__global__ void __launch_bounds__(256) fuse_kernel(const float* __restrict__ Hp,
                                                   const float* __restrict__ bias,
                                                   float* __restrict__ H,
                                                   float* __restrict__ parts) {
    constexpr int Q4G = NN * NOUT / 4;            // float4 per gene
    constexpr int EPT = Q4G / (64 * 256);         // 4 (NOUT=64) or 2 (NOUT=32)
    constexpr int CG  = NOUT / 4;                 // bias float4 groups
    const int g   = blockIdx.y;
    const int tid = threadIdx.x;

    const float4* p0 = (const float4*)(Hp + (size_t)(g * NR + 0) * NN * NOUT);
    const float4* p1 = (const float4*)(Hp + (size_t)(g * NR + 1) * NN * NOUT);
    float4* Hg = (float4*)(H + (size_t)g * NN * NOUT);
    const float4* bv = (const float4*)(bias + g * NOUT);

    float lsum = 0.f;
#pragma unroll
    for (int it = 0; it < EPT; ++it) {
        int idx = blockIdx.x * 256 + tid + it * (64 * 256);
        float4 a = p0[idx], b = p1[idx], bb = bv[idx % CG];
        float4 r;
        r.x = fmaxf(a.x + b.x + bb.x, 0.f);
        r.y = fmaxf(a.y + b.y + bb.y, 0.f);
        r.z = fmaxf(a.z + b.z + bb.z, 0.f);
        r.w = fmaxf(a.w + b.w + bb.w, 0.f);
        Hg[idx] = r;
        lsum += r.x + r.y + r.z + r.w;
    }
#pragma unroll
    for (int off = 16; off; off >>= 1) lsum += __shfl_xor_sync(0xffffffffu, lsum, off);
    __shared__ float wsum[8];
    if ((tid & 31) == 0) wsum[tid >> 5] = lsum;
    __syncthreads();
    if (tid == 0) {
        float s = 0.f;
#pragma unroll
        for (int w = 0; w < 8; ++w) s += wsum[w];
        parts[g * 64 + blockIdx.x] = s;
    }
}

// ---------------- attention over genes ----------------
__global__ void attn_kernel(const float* __restrict__ parts,
                            const float* __restrict__ Wk,
                            const float* __restrict__ Wq,
                            int layer, float inv_cnt,
                            float* __restrict__ a_out) {
    __shared__ float ssq[NG];
    const int tid = threadIdx.x;   // 96 threads: 3 warps, one per gene
    const int g = tid >> 5, lane = tid & 31;
    float v = parts[g * 64 + lane] + parts[g * 64 + 32 + lane];
#pragma unroll
    for (int off = 16; off; off >>= 1) v += __shfl_xor_sync(0xffffffffu, v, off);
    if (lane == 0) ssq[g] = v * inv_cnt;
    __syncthreads();
    if (tid == 0) {
        const float* wk = Wk + layer * 9;
        const float* wq = Wq + layer * 9;
        float kk[NG], lg[NG];
#pragma unroll
        for (int j = 0; j < NG; ++j)
            kk[j] = fmaxf(ssq[0] * wk[j] + ssq[1] * wk[3 + j] + ssq[2] * wk[6 + j], 0.f);
        float m = -1e30f;
#pragma unroll
        for (int j = 0; j < NG; ++j) {
            lg[j] = kk[0] * wq[j] + kk[1] * wq[3 + j] + kk[2] * wq[6 + j];
            m = fmaxf(m, lg[j]);
        }
        float e0 = expf(lg[0] - m), e1 = expf(lg[1] - m), e2 = expf(lg[2] - m);
        float inv = 1.f / (e0 + e1 + e2);
        a_out[0] = e0 * inv;
        a_out[1] = e1 * inv;
        a_out[2] = e2 * inv;
    }
}

// ---------------- attention-weighted combine: out = sum_g a[g] * H[g] ----------------
__global__ void combine_kernel(const float* __restrict__ H,
                               const float* __restrict__ a,
                               float* __restrict__ out, int nd) {
    const int i = blockIdx.x * blockDim.x + threadIdx.x;   // float4 index
    const int q = nd >> 2;
    if (i >= q) return;
    const float a0 = a[0], a1 = a[1], a2 = a[2];
    const float4* h = (const float4*)H;
    float4 x0 = h[i], x1 = h[i + q], x2 = h[i + 2 * q];
    float4 r;
    r.x = a0 * x0.x + a1 * x1.x + a2 * x2.x;
    r.y = a0 * x0.y + a1 * x1.y + a2 * x2.y;
    r.z = a0 * x0.z + a1 * x1.z + a2 * x2.z;
    r.w = a0 * x0.w + a1 * x1.w + a2 * x2.w;
    ((float4*)out)[i] = r;
}

// ---------------- launch ----------------
extern "C" void kernel_launch(void* const* d_in, const int* in_sizes, int n_in,
                              void* d_out, int out_size) {
    const float* x   = (const float*)d_in[0];
    const float* adj = (const float*)d_in[1];
    const float* W1  = (const float*)d_in[2];
    const float* b1  = (const float*)d_in[3];
    const float* W2  = (const float*)d_in[4];
    const float* b2  = (const float*)d_in[5];
    const float* Wk  = (const float*)d_in[6];
    const float* Wq  = (const float*)d_in[7];
    float* out = (float*)d_out;

    float *s1, *hp1, *h1, *xh, *s2, *hp2, *h2, *p1, *p2, *a1, *a2;
    cudaGetSymbolAddress((void**)&s1, g_s1);
    cudaGetSymbolAddress((void**)&hp1, g_hp1);
    cudaGetSymbolAddress((void**)&h1, g_h1);
    cudaGetSymbolAddress((void**)&xh, g_xh);
    cudaGetSymbolAddress((void**)&s2, g_s2);
    cudaGetSymbolAddress((void**)&hp2, g_hp2);
    cudaGetSymbolAddress((void**)&h2, g_h2);
    cudaGetSymbolAddress((void**)&p1, g_p1);
    cudaGetSymbolAddress((void**)&p2, g_p2);
    cudaGetSymbolAddress((void**)&a1, g_a1);
    cudaGetSymbolAddress((void**)&a2, g_a2);

    // Layer 1
    small_gemm<NHID><<<dim3(NN / 64, NG * NR), 256>>>(x, W1, s1);
    big_gemm2<NHID><<<dim3(64, NG, NR), 128>>>(adj, s1, hp1);
    fuse_kernel<NHID><<<dim3(64, NG), 256>>>(hp1, b1, h1, p1);
    attn_kernel<<<1, 96>>>(p1, Wk, Wq, 0, 1.f / ((float)NN * NHID), a1);
    combine_kernel<<<(NN * NHID / 4 + 255) / 256, 256>>>(h1, a1, xh, NN * NHID);

    // Layer 2
    small_gemm<NCLS><<<dim3(NN / 64, NG * NR), 256>>>(xh, W2, s2);
    big_gemm2<NCLS><<<dim3(64, NG, NR), 128>>>(adj, s2, hp2);
    fuse_kernel<NCLS><<<dim3(64, NG), 256>>>(hp2, b2, h2, p2);
    attn_kernel<<<1, 96>>>(p2, Wk, Wq, 1, 1.f / ((float)NN * NCLS), a2);
    combine_kernel<<<(NN * NCLS / 4 + 255) / 256, 256>>>(h2, a2, out, NN * NCLS);
}

// round 4
// speedup vs baseline: 1.5242x; 1.0626x over previous
#include <cuda_runtime.h>
#include <cuda_bf16.h>
#include <math.h>

// Problem constants
#define NN    4096
#define NFEAT 64
#define NHID  64
#define NCLS  32
#define NG    3
#define NR    2

// ---------------- device scratch (static, no allocation) ----------------
__device__ float g_s1[NG * NR * NN * NHID];
__device__ float g_hp1[NG * NR * NN * NHID];
__device__ float g_h1[NG * NN * NHID];
__device__ float g_s2[NG * NR * NN * NCLS];
__device__ float g_hp2[NG * NR * NN * NCLS];
__device__ float g_h2[NG * NN * NCLS];
__device__ float g_p1[NG * 64];
__device__ float g_p2[NG * 64];
__device__ float g_a1[NG];
__device__ float g_a2[NG];
__device__ int   g_cnt1;
__device__ int   g_cnt2;

// ---------------- helpers ----------------
__device__ __forceinline__ unsigned f2tf(float x) {
    unsigned r;
    asm("cvt.rna.tf32.f32 %0, %1;" : "=r"(r) : "f"(x));
    return r;
}

__device__ __forceinline__ void mma_tf32(float* d, const unsigned* a, const unsigned* b) {
    asm volatile(
        "mma.sync.aligned.m16n8k8.row.col.f32.tf32.tf32.f32 "
        "{%0,%1,%2,%3}, {%4,%5,%6,%7}, {%8,%9}, {%0,%1,%2,%3};"
        : "+f"(d[0]), "+f"(d[1]), "+f"(d[2]), "+f"(d[3])
        : "r"(a[0]), "r"(a[1]), "r"(a[2]), "r"(a[3]), "r"(b[0]), "r"(b[1]));
}

__device__ __forceinline__ void cp16(void* smem_dst, const void* gsrc) {
    unsigned d = (unsigned)__cvta_generic_to_shared(smem_dst);
    asm volatile("cp.async.cg.shared.global [%0], [%1], 16;" :: "r"(d), "l"(gsrc));
}
#define CP_COMMIT() asm volatile("cp.async.commit_group;")

// ---------------- small fp32 GEMM: OUT[gr] = tf32(IN @ W[gr]) ----------------
template <int NOUT>
__global__ void __launch_bounds__(256) small_gemm(const float* __restrict__ IN,
                                                  const float* __restrict__ W,
                                                  float* __restrict__ OUT) {
    __shared__ float Xs[64][65];
    __shared__ float Ws[64][NOUT + 1];
    const int tid  = threadIdx.x;
    const int row0 = blockIdx.x * 64;
    const int gr   = blockIdx.y;

#pragma unroll
    for (int it = 0; it < 16; ++it) {
        int idx = tid + it * 256;
        Xs[idx >> 6][idx & 63] = IN[(size_t)(row0 + (idx >> 6)) * 64 + (idx & 63)];
    }
    const float* Wg = W + (size_t)gr * 64 * NOUT;
#pragma unroll
    for (int it = 0; it < (64 * NOUT) / 256; ++it) {
        int idx = tid + it * 256;
        Ws[idx / NOUT][idx % NOUT] = Wg[idx];
    }
    __syncthreads();

    constexpr int TX  = NOUT / 4;
    constexpr int TY  = 256 / TX;
    constexpr int RPT = 64 / TY;
    const int tx = tid % TX, ty = tid / TX;
    const int c0 = tx * 4, r0 = ty * RPT;

    float acc[RPT][4];
#pragma unroll
    for (int i = 0; i < RPT; ++i)
#pragma unroll
        for (int j = 0; j < 4; ++j) acc[i][j] = 0.f;

#pragma unroll
    for (int k = 0; k < 64; ++k) {
        float bb[4];
#pragma unroll
        for (int j = 0; j < 4; ++j) bb[j] = Ws[k][c0 + j];
#pragma unroll
        for (int i = 0; i < RPT; ++i) {
            float av = Xs[r0 + i][k];
#pragma unroll
            for (int j = 0; j < 4; ++j) acc[i][j] = fmaf(av, bb[j], acc[i][j]);
        }
    }
    float* Og = OUT + ((size_t)gr * NN + row0) * NOUT;
#pragma unroll
    for (int i = 0; i < RPT; ++i)
#pragma unroll
        for (int j = 0; j < 4; ++j)
            Og[(size_t)(r0 + i) * NOUT + c0 + j] = __uint_as_float(f2tf(acc[i][j]));
}

// ---------------- combine + small GEMM (layer 2 projection) ----------------
// xh = sum_g a[g]*H[g]  (built per-tile in smem), OUT[gr] = tf32(xh @ W[gr])
// grid (64, 6), 256 threads.
__global__ void __launch_bounds__(256) combine_gemm(const float* __restrict__ H,
                                                    const float* __restrict__ a,
                                                    const float* __restrict__ W,
                                                    float* __restrict__ OUT) {
    constexpr int NOUT = NCLS;
    __shared__ float Xs[64][65];
    __shared__ float Ws[64][NOUT + 1];
    const int tid  = threadIdx.x;
    const int row0 = blockIdx.x * 64;
    const int gr   = blockIdx.y;
    const float a0 = a[0], a1v = a[1], a2v = a[2];

    const size_t gstride = (size_t)NN * NHID;
#pragma unroll
    for (int it = 0; it < 16; ++it) {
        int idx = tid + it * 256;
        int r = idx >> 6, c = idx & 63;
        size_t off = (size_t)(row0 + r) * NHID + c;
        Xs[r][c] = a0 * H[off] + a1v * H[off + gstride] + a2v * H[off + 2 * gstride];
    }
    const float* Wg = W + (size_t)gr * 64 * NOUT;
#pragma unroll
    for (int it = 0; it < (64 * NOUT) / 256; ++it) {
        int idx = tid + it * 256;
        Ws[idx / NOUT][idx % NOUT] = Wg[idx];
    }
    __syncthreads();

    constexpr int TX  = NOUT / 4;   // 8
    constexpr int TY  = 256 / TX;   // 32
    constexpr int RPT = 64 / TY;    // 2
    const int tx = tid % TX, ty = tid / TX;
    const int c0 = tx * 4, r0 = ty * RPT;

    float acc[RPT][4];
#pragma unroll
    for (int i = 0; i < RPT; ++i)
#pragma unroll
        for (int j = 0; j < 4; ++j) acc[i][j] = 0.f;

#pragma unroll
    for (int k = 0; k < 64; ++k) {
        float bb[4];
#pragma unroll
        for (int j = 0; j < 4; ++j) bb[j] = Ws[k][c0 + j];
#pragma unroll
        for (int i = 0; i < RPT; ++i) {
            float av = Xs[r0 + i][k];
#pragma unroll
            for (int j = 0; j < 4; ++j) acc[i][j] = fmaf(av, bb[j], acc[i][j]);
        }
    }
    float* Og = OUT + ((size_t)gr * NN + row0) * NOUT;
#pragma unroll
    for (int i = 0; i < RPT; ++i)
#pragma unroll
        for (int j = 0; j < 4; ++j)
            Og[(size_t)(r0 + i) * NOUT + c0 + j] = __uint_as_float(f2tf(acc[i][j]));
}

// ---------------- big GEMM (role-split, 4-stage pipeline) ----------------
// Hp[g,r] = adj[g,r] @ S[g,r]; grid (64,3,2), 128 threads, dynamic smem.
template <int NOUT>
__global__ void __launch_bounds__(128) big_gemm2(const float* __restrict__ adj,
                                                 const float* __restrict__ S,
                                                 float* __restrict__ Hp) {
    constexpr int TM = 64;
    constexpr int KB = 32;
    constexpr int ST = 4;
    constexpr int AP = 36;                    // 36 mod 32 == 4 -> conflict free
    constexpr int BP = NOUT + 8;              // stride mod 32 == 8 -> conflict free
    constexpr int WN = (NOUT == 64) ? 32 : 16;
    constexpr int MI = 2;
    constexpr int NJ = WN / 8;

    extern __shared__ float dyn[];
    float (*As)[TM][AP] = (float (*)[TM][AP])dyn;
    float (*Bs)[KB][BP] = (float (*)[KB][BP])(dyn + ST * TM * AP);

    const int g    = blockIdx.y;
    const int role = blockIdx.z;
    const int row0 = blockIdx.x * TM;
    const int tid  = threadIdx.x;
    const int warp = tid >> 5, lane = tid & 31;
    const int gid  = lane >> 2, tg = lane & 3;
    const int wm   = warp >> 1, wn = warp & 1;
    const int wrow = wm * 32, wcol = wn * WN;

    float acc[MI][NJ][4];
#pragma unroll
    for (int i = 0; i < MI; ++i)
#pragma unroll
        for (int j = 0; j < NJ; ++j)
#pragma unroll
            for (int q = 0; q < 4; ++q) acc[i][j][q] = 0.f;

    const float* Ag = adj + ((size_t)(g * NR + role) * NN + row0) * NN;
    const float* Sg = S + (size_t)(g * NR + role) * NN * NOUT;

    auto load_chunk = [&](int buf, int c) {
#pragma unroll
        for (int it = 0; it < 4; ++it) {
            int cid = tid + it * 128;
            int r = cid >> 3, s4 = (cid & 7) * 4;
            cp16(&As[buf][r][s4], Ag + (size_t)r * NN + c * KB + s4);
        }
        constexpr int SEGS = NOUT / 4;
#pragma unroll
        for (int it = 0; it < (KB * NOUT / 4) / 128; ++it) {
            int cid = tid + it * 128;
            int r = cid / SEGS, s4 = (cid % SEGS) * 4;
            cp16(&Bs[buf][r][s4], Sg + (size_t)(c * KB + r) * NOUT + s4);
        }
    };

    constexpr int NCH = NN / KB;   // 128
#pragma unroll
    for (int i = 0; i < ST - 1; ++i) {
        load_chunk(i, i);
        CP_COMMIT();
    }

    for (int c = 0; c < NCH; ++c) {
        if (c + ST - 1 < NCH) load_chunk((c + ST - 1) % ST, c + ST - 1);
        CP_COMMIT();                                   // possibly empty group
        asm volatile("cp.async.wait_group 3;");        // chunk c complete
        __syncthreads();
        const int buf = c % ST;
#pragma unroll
        for (int ks = 0; ks < KB / 8; ++ks) {
            const int k0 = ks * 8;
            unsigned afr[MI][4];
#pragma unroll
            for (int i = 0; i < MI; ++i) {
                int rb = wrow + i * 16;
                afr[i][0] = f2tf(As[buf][rb + gid][k0 + tg]);
                afr[i][1] = f2tf(As[buf][rb + gid + 8][k0 + tg]);
                afr[i][2] = f2tf(As[buf][rb + gid][k0 + tg + 4]);
                afr[i][3] = f2tf(As[buf][rb + gid + 8][k0 + tg + 4]);
            }
            unsigned bfr[NJ][2];
#pragma unroll
            for (int j = 0; j < NJ; ++j) {
                int cb = wcol + j * 8 + gid;
                bfr[j][0] = __float_as_uint(Bs[buf][k0 + tg][cb]);
                bfr[j][1] = __float_as_uint(Bs[buf][k0 + tg + 4][cb]);
            }
#pragma unroll
            for (int i = 0; i < MI; ++i)
#pragma unroll
                for (int j = 0; j < NJ; ++j)
                    mma_tf32(acc[i][j], afr[i], bfr[j]);
        }
        __syncthreads();
    }

    float* Hg = Hp + ((size_t)(g * NR + role) * NN + row0) * NOUT;
#pragma unroll
    for (int i = 0; i < MI; ++i) {
#pragma unroll
        for (int j = 0; j < NJ; ++j) {
            const int r0 = wrow + i * 16 + gid;
            const int cc = wcol + j * 8 + tg * 2;
            *(float2*)&Hg[(size_t)r0 * NOUT + cc]       = make_float2(acc[i][j][0], acc[i][j][1]);
            *(float2*)&Hg[(size_t)(r0 + 8) * NOUT + cc] = make_float2(acc[i][j][2], acc[i][j][3]);
        }
    }
}

// ---------------- fuse + attention (last-block) ----------------
// H[g] = relu(Hp[g,0]+Hp[g,1]+b[g]); parts -> last CTA computes softmax weights.
template <int NOUT>
__global__ void __launch_bounds__(256) fuse_attn(const float* __restrict__ Hp,
                                                 const float* __restrict__ bias,
                                                 const float* __restrict__ Wk,
                                                 const float* __restrict__ Wq,
                                                 int layer, float inv_cnt,
                                                 float* __restrict__ H,
                                                 float* __restrict__ parts,
                                                 float* __restrict__ a_out,
                                                 int* __restrict__ cnt) {
    constexpr int Q4G = NN * NOUT / 4;
    constexpr int EPT = Q4G / (64 * 256);
    constexpr int CG  = NOUT / 4;
    const int g   = blockIdx.y;
    const int tid = threadIdx.x;

    const float4* p0 = (const float4*)(Hp + (size_t)(g * NR + 0) * NN * NOUT);
    const float4* p1 = (const float4*)(Hp + (size_t)(g * NR + 1) * NN * NOUT);
    float4* Hg = (float4*)(H + (size_t)g * NN * NOUT);
    const float4* bv = (const float4*)(bias + g * NOUT);

    float lsum = 0.f;
#pragma unroll
    for (int it = 0; it < EPT; ++it) {
        int idx = blockIdx.x * 256 + tid + it * (64 * 256);
        float4 a = p0[idx], b = p1[idx], bb = bv[idx % CG];
        float4 r;
        r.x = fmaxf(a.x + b.x + bb.x, 0.f);
        r.y = fmaxf(a.y + b.y + bb.y, 0.f);
        r.z = fmaxf(a.z + b.z + bb.z, 0.f);
        r.w = fmaxf(a.w + b.w + bb.w, 0.f);
        Hg[idx] = r;
        lsum += r.x + r.y + r.z + r.w;
    }
#pragma unroll
    for (int off = 16; off; off >>= 1) lsum += __shfl_xor_sync(0xffffffffu, lsum, off);
    __shared__ float wsum[8];
    if ((tid & 31) == 0) wsum[tid >> 5] = lsum;
    __syncthreads();
    if (tid == 0) {
        float s = 0.f;
#pragma unroll
        for (int w = 0; w < 8; ++w) s += wsum[w];
        parts[g * 64 + blockIdx.x] = s;
    }

    // last-block attention
    __threadfence();
    __shared__ int lastb;
    if (tid == 0) lastb = (atomicAdd(cnt, 1) == 64 * NG - 1) ? 1 : 0;
    __syncthreads();
    if (!lastb) return;

    __shared__ float ssq[NG];
    if (tid < NG) {
        float s = 0.f;
        for (int i = 0; i < 64; ++i) s += parts[tid * 64 + i];   // fixed order: deterministic
        ssq[tid] = s * inv_cnt;
    }
    __syncthreads();
    if (tid == 0) {
        const float* wk = Wk + layer * 9;
        const float* wq = Wq + layer * 9;
        float kk[NG], lg[NG];
#pragma unroll
        for (int j = 0; j < NG; ++j)
            kk[j] = fmaxf(ssq[0] * wk[j] + ssq[1] * wk[3 + j] + ssq[2] * wk[6 + j], 0.f);
        float m = -1e30f;
#pragma unroll
        for (int j = 0; j < NG; ++j) {
            lg[j] = kk[0] * wq[j] + kk[1] * wq[3 + j] + kk[2] * wq[6 + j];
            m = fmaxf(m, lg[j]);
        }
        float e0 = expf(lg[0] - m), e1 = expf(lg[1] - m), e2 = expf(lg[2] - m);
        float inv = 1.f / (e0 + e1 + e2);
        a_out[0] = e0 * inv;
        a_out[1] = e1 * inv;
        a_out[2] = e2 * inv;
        *cnt = 0;   // reset for next launch / replay
    }
}

// ---------------- final combine: out = sum_g a[g] * H[g] ----------------
__global__ void combine_kernel(const float* __restrict__ H,
                               const float* __restrict__ a,
                               float* __restrict__ out, int nd) {
    const int i = blockIdx.x * blockDim.x + threadIdx.x;
    const int q = nd >> 2;
    if (i >= q) return;
    const float a0 = a[0], a1 = a[1], a2 = a[2];
    const float4* h = (const float4*)H;
    float4 x0 = h[i], x1 = h[i + q], x2 = h[i + 2 * q];
    float4 r;
    r.x = a0 * x0.x + a1 * x1.x + a2 * x2.x;
    r.y = a0 * x0.y + a1 * x1.y + a2 * x2.y;
    r.z = a0 * x0.z + a1 * x1.z + a2 * x2.z;
    r.w = a0 * x0.w + a1 * x1.w + a2 * x2.w;
    ((float4*)out)[i] = r;
}

// ---------------- launch ----------------
extern "C" void kernel_launch(void* const* d_in, const int* in_sizes, int n_in,
                              void* d_out, int out_size) {
    const float* x   = (const float*)d_in[0];
    const float* adj = (const float*)d_in[1];
    const float* W1  = (const float*)d_in[2];
    const float* b1  = (const float*)d_in[3];
    const float* W2  = (const float*)d_in[4];
    const float* b2  = (const float*)d_in[5];
    const float* Wk  = (const float*)d_in[6];
    const float* Wq  = (const float*)d_in[7];
    float* out = (float*)d_out;

    float *s1, *hp1, *h1, *s2, *hp2, *h2, *p1, *p2, *a1, *a2;
    int *c1, *c2;
    cudaGetSymbolAddress((void**)&s1, g_s1);
    cudaGetSymbolAddress((void**)&hp1, g_hp1);
    cudaGetSymbolAddress((void**)&h1, g_h1);
    cudaGetSymbolAddress((void**)&s2, g_s2);
    cudaGetSymbolAddress((void**)&hp2, g_hp2);
    cudaGetSymbolAddress((void**)&h2, g_h2);
    cudaGetSymbolAddress((void**)&p1, g_p1);
    cudaGetSymbolAddress((void**)&p2, g_p2);
    cudaGetSymbolAddress((void**)&a1, g_a1);
    cudaGetSymbolAddress((void**)&a2, g_a2);
    cudaGetSymbolAddress((void**)&c1, g_cnt1);
    cudaGetSymbolAddress((void**)&c2, g_cnt2);

    constexpr int SM64 = 4 * (64 * 36 + 32 * (NHID + 8)) * 4;   // 73728 B
    constexpr int SM32 = 4 * (64 * 36 + 32 * (NCLS + 8)) * 4;   // 57344 B
    cudaFuncSetAttribute(big_gemm2<NHID>, cudaFuncAttributeMaxDynamicSharedMemorySize, SM64);
    cudaFuncSetAttribute(big_gemm2<NCLS>, cudaFuncAttributeMaxDynamicSharedMemorySize, SM32);

    // Layer 1
    small_gemm<NHID><<<dim3(NN / 64, NG * NR), 256>>>(x, W1, s1);
    big_gemm2<NHID><<<dim3(64, NG, NR), 128, SM64>>>(adj, s1, hp1);
    fuse_attn<NHID><<<dim3(64, NG), 256>>>(hp1, b1, Wk, Wq, 0, 1.f / ((float)NN * NHID),
                                           h1, p1, a1, c1);
    // Layer 2 (combine fused into projection)
    combine_gemm<<<dim3(NN / 64, NG * NR), 256>>>(h1, a1, W2, s2);
    big_gemm2<NCLS><<<dim3(64, NG, NR), 128, SM32>>>(adj, s2, hp2);
    fuse_attn<NCLS><<<dim3(64, NG), 256>>>(hp2, b2, Wk, Wq, 1, 1.f / ((float)NN * NCLS),
                                           h2, p2, a2, c2);
    combine_kernel<<<(NN * NCLS / 4 + 255) / 256, 256>>>(h2, a2, out, NN * NCLS);
}